// round 16
// baseline (speedup 1.0000x reference)
#include <cuda_runtime.h>
#include <cuda_bf16.h>

// Canny edge detection, exact replica of the JAX reference.
// Strip view: (B*H, W) = (8192, 512). Bitmask: 8 u64 (16 u32) words per row.

#define HH 8192
#define WD 512
#define TROWS 320          // hysteresis tile rows: 64 interior + 2*128 halo
#define HALO 128
#define INT_ROWS 64
#define HPITCH 9           // padded u64 pitch in shared
#define NB 128             // hysteresis grid size (<= #SMs -> co-resident)

__device__ unsigned long long g_strong[HH * 8];
__device__ unsigned long long g_weak[HH * 8];
__device__ unsigned long long g_tmp[HH * 8];
__device__ int g_conv[4];
__device__ int g_count;
__device__ volatile int g_sense;

__device__ __forceinline__ float quant(float v) {
    // input in [-1,1) -> result already in [0,255]; clip is redundant
    return floorf(((v + 1.0f) * 0.5f) * 255.0f);
}

// ---------------------------------------------------------------------------
// Kernel 1: quantize -> Sobel (replicate pad on strip) -> channel argmax ->
//   NMS direction code -> thresholds -> strong/weak bitmasks.
// 16x64 output tile, 256 threads, grid (8,512). smem 22 KB -> 8 blocks/SM.
//   P1: quantized 20x72x3 f32 img tile, float4 quads (scalar clamp fallback
//       only for the 2 out-of-range boundary quads at x-edges).
//   P2: 18x66 mag region, 2 px/item via float2 loads; packs mag|code<<16,
//       zero-stores words outside the global image (NMS zero-pad).
//   P3: center + 2 code-directed neighbor reads, ballot packs bits.
// All arithmetic integer-exact in f32 -> bit-identical to the reference.
// ---------------------------------------------------------------------------
#define SIMW 72            // simg row pitch; index j <-> GX = x0-4+j

__global__ __launch_bounds__(256) void k_grad(const float* __restrict__ xin) {
    __shared__ __align__(16) float simg[3][20][SIMW];
    __shared__ __align__(16) unsigned smag[18][68];

    const int tid = threadIdx.x;
    const int x0 = blockIdx.x * 64;
    const int Y0 = blockIdx.y * 16;
    const float TG22 = 0.4142135623730951f;

    if (blockIdx.x == 0 && blockIdx.y == 0 && tid < 4) g_conv[tid] = 0;

    // Phase 1: quantized img tile. 20 rows x 18 quads of 4 floats.
    for (int item = tid; item < 360; item += 256) {
        int row = item / 18, q = item - row * 18;
        int GY = Y0 - 2 + row;
        GY = max(0, min(HH - 1, GY));                 // replicate clamp (strip)
        int b = GY >> 9, y = GY & 511;
        const float* base = xin + (size_t)((b * 1536 + y) * 512);
        int GXq = x0 - 4 + 4 * q;
        if ((unsigned)GXq <= 508u) {                  // fully in-range quad
            float4 v0 = *(const float4*)(base + GXq);
            float4 v1 = *(const float4*)(base + (1 << 18) + GXq);
            float4 v2 = *(const float4*)(base + (2 << 18) + GXq);
            *(float4*)&simg[0][row][4 * q] =
                make_float4(quant(v0.x), quant(v0.y), quant(v0.z), quant(v0.w));
            *(float4*)&simg[1][row][4 * q] =
                make_float4(quant(v1.x), quant(v1.y), quant(v1.z), quant(v1.w));
            *(float4*)&simg[2][row][4 * q] =
                make_float4(quant(v2.x), quant(v2.y), quant(v2.z), quant(v2.w));
        } else {                                      // boundary quad: clamp X
#pragma unroll
            for (int j = 0; j < 4; ++j) {
                int GX = min(max(GXq + j, 0), WD - 1);
                simg[0][row][4 * q + j] = quant(base[GX]);
                simg[1][row][4 * q + j] = quant(base[(1 << 18) + GX]);
                simg[2][row][4 * q + j] = quant(base[(2 << 18) + GX]);
            }
        }
    }
    __syncthreads();

    // Phase 2: mag+code for 18 rows x 66 cols (2 px per item, float2 loads).
    // mag[m][cc] center = img row m+1, GX = x0-1+cc  (simg index cc+3).
    for (int item = tid; item < 594; item += 256) {
        int m  = item / 33;
        int tp = item - m * 33;
        int cc = 2 * tp;
        float bm0 = -1.0f, bgx0 = 0.0f, bgy0 = 0.0f;
        float bm1 = -1.0f, bgx1 = 0.0f, bgy1 = 0.0f;
#pragma unroll
        for (int ch = 0; ch < 3; ++ch) {
            const float* ip = &simg[ch][m][cc + 2];
            float2 p00 = *(const float2*)(ip);
            float2 p01 = *(const float2*)(ip + 2);
            float2 p10 = *(const float2*)(ip + SIMW);
            float2 p11 = *(const float2*)(ip + SIMW + 2);
            float2 p20 = *(const float2*)(ip + 2 * SIMW);
            float2 p21 = *(const float2*)(ip + 2 * SIMW + 2);
            float aL0 = p00.x + 2.0f * p00.y + p01.x;
            float aR0 = p00.y + 2.0f * p01.x + p01.y;
            float dL0 = p01.x - p00.x, dR0 = p01.y - p00.y;
            float aL1 = p10.x + 2.0f * p10.y + p11.x;
            float aR1 = p10.y + 2.0f * p11.x + p11.y;
            float dL1 = p11.x - p10.x, dR1 = p11.y - p10.y;
            float aL2 = p20.x + 2.0f * p20.y + p21.x;
            float aR2 = p20.y + 2.0f * p21.x + p21.y;
            float dL2 = p21.x - p20.x, dR2 = p21.y - p20.y;
            float gxL = dL0 + 2.0f * dL1 + dL2, gyL = aL2 - aL0;
            float gxR = dR0 + 2.0f * dR1 + dR2, gyR = aR2 - aR0;
            float mgL = fabsf(gxL) + fabsf(gyL);
            float mgR = fabsf(gxR) + fabsf(gyR);
            if (mgL > bm0) { bm0 = mgL; bgx0 = gxL; bgy0 = gyL; }
            if (mgR > bm1) { bm1 = mgR; bgx1 = gxR; bgy1 = gyR; }
        }
        int t = Y0 - 1 + m;
        bool trow = (unsigned)t < (unsigned)HH;
        {
            int X = x0 - 1 + cc;
            unsigned wv = 0u;
            if (trow && (unsigned)X < (unsigned)WD) {
                float ax = fabsf(bgx0), ay = fabsf(bgy0);
                unsigned code = (ay < TG22 * ax) ? 0u
                              : ((ay * TG22 > ax) ? 1u
                              : ((bgx0 * bgy0 >= 0.0f) ? 2u : 3u));
                wv = (unsigned)(int)bm0 | (code << 16);
            }
            smag[m][cc] = wv;
        }
        {
            int X = x0 + cc;
            unsigned wv = 0u;
            if (trow && (unsigned)X < (unsigned)WD) {
                float ax = fabsf(bgx1), ay = fabsf(bgy1);
                unsigned code = (ay < TG22 * ax) ? 0u
                              : ((ay * TG22 > ax) ? 1u
                              : ((bgx1 * bgy1 >= 0.0f) ? 2u : 3u));
                wv = (unsigned)(int)bm1 | (code << 16);
            }
            smag[m][cc + 1] = wv;
        }
    }
    __syncthreads();

    // Phase 3: NMS compares + thresholds; ballot packs 32 cols per write.
    // n1 offsets: code 0 (h): (0,-1); 1 (v): (-1,0); 2: (-1,-1); 3: (-1,+1).
    const unsigned FULL = 0xffffffffu;
    const int lane = tid & 31;
    for (int i = tid; i < 1024; i += 256) {
        int py = i >> 6, pxc = i & 63;
        const unsigned* sp = &smag[0][0] + (py + 1) * 68 + (pxc + 1);
        unsigned w = sp[0];
        int mg = (int)(w & 0xFFFFu);
        unsigned code = w >> 16;
        int off = (code == 0u) ? -1
                : ((code == 1u) ? -68 : ((code == 2u) ? -69 : -67));
        int n1 = (int)(sp[off]  & 0xFFFFu);   // OOB words are 0 (zero-pad)
        int n2 = (int)(sp[-off] & 0xFFFFu);
        bool keep   = (mg > n1) && (mg >= n2);
        bool strong = keep && (mg > 200);
        bool weak   = keep && (mg > 100);
        unsigned bs = __ballot_sync(FULL, strong);
        unsigned bw = __ballot_sync(FULL, weak);
        if (lane == 0) {
            int u32idx = (Y0 + py) * 16 + (x0 >> 5) + (pxc >> 5);
            ((unsigned*)g_strong)[u32idx] = bs;
            ((unsigned*)g_weak)[u32idx]   = bw;
        }
    }
}

// ---------------------------------------------------------------------------
// Software grid barrier (sense-reversing; classic threadFenceReduction
// pattern). Valid because grid = 128 blocks <= SM count -> all co-resident.
// ---------------------------------------------------------------------------
__device__ __forceinline__ void gbar() {
    __threadfence();
    __syncthreads();
    if (threadIdx.x == 0) {
        int s = g_sense;
        if (atomicAdd(&g_count, 1) == NB - 1) {
            g_count = 0;
            __threadfence();
            g_sense = 1 - s;
        } else {
            while (g_sense == s) __nanosleep(64);
        }
        __threadfence();
    }
    __syncthreads();
}

// ---------------------------------------------------------------------------
// Kernel 2: ALL of hysteresis in one persistent kernel — 4 phases of (up to)
// 128 exact Jacobi dilation steps (= the reference's 512-step cap,
// bit-exact), separated by grid barriers. Each block keeps its interior +
// weak masks resident; between phases only the 256 halo rows are reloaded.
// Per-phase global convergence detection ("no change at first step in every
// tile" <=> global fixed point, since windows hold the exact global state at
// phase start) skips remaining phases. Finally expands interior rows
// straight to the float output.
// ---------------------------------------------------------------------------
__global__ __launch_bounds__(512) void k_hyst_all(float* __restrict__ out) {
    __shared__ unsigned long long bufA[TROWS * HPITCH];
    __shared__ unsigned long long bufB[TROWS * HPITCH];
    __shared__ int sh_done;

    const int tid = threadIdx.x;
    const int base = blockIdx.x * INT_ROWS;

    for (int i = tid; i < TROWS * 8; i += 512) {
        int r = i >> 3, cc = i & 7;
        int gr = base - HALO + r;
        bufA[r * HPITCH + cc] = (gr >= 0 && gr < HH) ? g_strong[gr * 8 + cc] : 0ull;
    }

    const int c = tid & 7;
    const int r0 = (tid >> 3) * 5;
    unsigned long long swr[5];
#pragma unroll
    for (int k = 0; k < 5; ++k) {
        int gr = base - HALO + r0 + k;
        swr[k] = (gr >= 0 && gr < HH) ? g_weak[gr * 8 + c] : 0ull;
    }
    __syncthreads();

    unsigned long long* cur = bufA;
    unsigned long long* nxt = bufB;
    unsigned long long* bufs[2] = { g_tmp, g_strong };

    for (int phase = 0; phase < 4; ++phase) {
        if (phase > 0) {
            // reload only halo rows from the buffer written in phase-1
            const unsigned long long* rb = bufs[(phase + 1) & 1];
            for (int i = tid; i < 256 * 8; i += 512) {
                int rh = i >> 3, cc = i & 7;
                int r = (rh < HALO) ? rh : rh + INT_ROWS;
                int gr = base - HALO + r;
                cur[r * HPITCH + cc] = (gr >= 0 && gr < HH) ? rb[gr * 8 + cc] : 0ull;
            }
            __syncthreads();
        }

        bool conv0 = false;
        for (int it = 0; it < 128; ++it) {
            auto hload = [&](int r, unsigned long long& h, unsigned long long& w) {
                if ((unsigned)r >= (unsigned)TROWS) { h = 0ull; w = 0ull; return; }
                unsigned long long ww = cur[r * HPITCH + c];
                unsigned long long wl = (c > 0) ? cur[r * HPITCH + c - 1] : 0ull;
                unsigned long long wr = (c < 7) ? cur[r * HPITCH + c + 1] : 0ull;
                w = ww;
                h = ww | (ww << 1) | (ww >> 1) | (wl >> 63) | (wr << 63);
            };
            unsigned long long Hm, H0, Hp, w0, wp, wd;
            hload(r0 - 1, Hm, wd);
            hload(r0, H0, w0);
            bool changed = false;
#pragma unroll
            for (int k = 0; k < 5; ++k) {
                hload(r0 + k + 1, Hp, wp);
                unsigned long long nw = ((Hm | H0 | Hp) & swr[k]) | w0;
                nxt[(r0 + k) * HPITCH + c] = nw;
                changed |= (nw != w0);
                Hm = H0; H0 = Hp; w0 = wp;
            }
            int any = __syncthreads_or(changed ? 1 : 0);
            unsigned long long* t = cur; cur = nxt; nxt = t;
            if (!any) { if (it == 0) conv0 = true; break; }
        }

        if (phase == 3) break;

        // publish interior rows for neighbors
        unsigned long long* wb = bufs[phase & 1];
        for (int i = tid; i < INT_ROWS * 8; i += 512) {
            int rr = i >> 3, cc = i & 7;
            wb[(base + rr) * 8 + cc] = cur[(HALO + rr) * HPITCH + cc];
        }
        if (tid == 0 && conv0) atomicAdd(&g_conv[phase], 1);

        gbar();

        if (tid == 0) sh_done = (atomicAdd(&g_conv[phase], 0) == NB);
        __syncthreads();
        if (sh_done) break;    // global fixed point: remaining phases identity
    }

    // expand interior rows to (B,3,H,W) floats in {-1,+1}
    for (int i = tid; i < INT_ROWS * 128; i += 512) {
        int rr = i >> 7, qx = i & 127;
        int t = base + rr, X = qx << 2;
        unsigned long long w = cur[(HALO + rr) * HPITCH + (X >> 6)];
        int sh = X & 63;
        float4 v;
        v.x = ((w >> sh) & 1ull) ? 1.0f : -1.0f;
        v.y = ((w >> (sh + 1)) & 1ull) ? 1.0f : -1.0f;
        v.z = ((w >> (sh + 2)) & 1ull) ? 1.0f : -1.0f;
        v.w = ((w >> (sh + 3)) & 1ull) ? 1.0f : -1.0f;
        int b = t >> 9, y = t & 511;
#pragma unroll
        for (int ch = 0; ch < 3; ++ch)
            *(float4*)&out[(size_t)((b * 3 + ch) * 262144 + y * 512 + X)] = v;
    }
}

extern "C" void kernel_launch(void* const* d_in, const int* in_sizes, int n_in,
                              void* d_out, int out_size) {
    const float* x = (const float*)d_in[0];
    float* out = (float*)d_out;

    dim3 g1(WD / 64, HH / 16);                  // (8, 512)
    k_grad<<<g1, 256>>>(x);
    k_hyst_all<<<NB, 512>>>(out);               // 512-step-capped fixed point
}